// round 10
// baseline (speedup 1.0000x reference)
#include <cuda_runtime.h>
#include <cuda_fp16.h>
#include <math.h>
#include <stdint.h>

#define Bdim 2
#define Tdim 4096
#define Cdim 2048
#define HSZ  64
#define Mrows 8192
static const size_t BTC = (size_t)Mrows * Cdim;

// ---------------- scratch ----------------
__device__ __half g_xr[(size_t)Mrows * Cdim];
__device__ __half g_xw[(size_t)Mrows * Cdim];
__device__ __half g_xk[(size_t)Mrows * Cdim];
__device__ __half g_xv[(size_t)Mrows * Cdim];
__device__ __half g_xa[(size_t)Mrows * Cdim];
__device__ __half g_xg[(size_t)Mrows * Cdim];
__device__ __half g_wr[(size_t)Cdim * Cdim];
__device__ __half g_wk[(size_t)Cdim * Cdim];
__device__ __half g_wv[(size_t)Cdim * Cdim];
__device__ __half g_w1p[(size_t)128 * Cdim];
__device__ __half g_a1p[(size_t)128 * Cdim];
__device__ __half g_v1p[(size_t)128 * Cdim];
__device__ __half g_g1p[(size_t)256 * Cdim];
__device__ __half g_w2p[(size_t)Cdim * 128];
__device__ __half g_a2p[(size_t)Cdim * 128];
__device__ __half g_v2p[(size_t)Cdim * 128];
__device__ __half g_g2p[(size_t)Cdim * 256];
__device__ __half g_hw[(size_t)Mrows * 128];
__device__ __half g_ha[(size_t)Mrows * 128];
__device__ __half g_hv[(size_t)Mrows * 128];
__device__ __half g_hg[(size_t)Mrows * 256];
__device__ float  g_ko[(size_t)Mrows * Cdim];
__device__ float  g_vg[(size_t)Mrows * Cdim];

// ---------------- helpers ----------------
__device__ __forceinline__ float sigmoidf_(float y) { return 1.0f / (1.0f + expf(-y)); }

__device__ __forceinline__ uint32_t smem_u32(const void* p) {
    uint32_t a;
    asm("{ .reg .u64 t; cvta.to.shared.u64 t, %1; cvt.u32.u64 %0, t; }" : "=r"(a) : "l"(p));
    return a;
}
__device__ __forceinline__ void mma16(float* d, const uint32_t* a, const uint32_t* b) {
    asm volatile("mma.sync.aligned.m16n8k16.row.col.f32.f16.f16.f32 "
        "{%0,%1,%2,%3}, {%4,%5,%6,%7}, {%8,%9}, {%0,%1,%2,%3};"
        : "+f"(d[0]), "+f"(d[1]), "+f"(d[2]), "+f"(d[3])
        : "r"(a[0]), "r"(a[1]), "r"(a[2]), "r"(a[3]), "r"(b[0]), "r"(b[1]));
}
__device__ __forceinline__ void cpa16(uint32_t dst, const __half* src) {
    asm volatile("cp.async.cg.shared.global [%0], [%1], 16;"
        :: "r"(dst), "l"(__cvta_generic_to_global(src)));
}
#define CP_COMMIT() asm volatile("cp.async.commit_group;" ::: "memory")
#define CP_WAIT1()  asm volatile("cp.async.wait_group 1;" ::: "memory")
#define LDSM4(r0,r1,r2,r3,addr) \
    asm volatile("ldmatrix.sync.aligned.m8n8.x4.shared.b16 {%0,%1,%2,%3}, [%4];" \
        : "=r"(r0), "=r"(r1), "=r"(r2), "=r"(r3) : "r"(addr))

// stage: per operand 128 rows x 64 halves (128B/row) = 16KB; A+B = 32KB; 3 stages
#define STG_OP 16384
#define STG_T  (2 * STG_OP)
#define SMEM_TOT (3 * STG_T)    // 98304 bytes

// ---------------- mainloop: 128x128 tile, KC=64, 3-stage cp.async, ldmatrix ----
__device__ __forceinline__ void mainloop64(
    const __half* __restrict__ A, const __half* __restrict__ Bm,
    int K, int m0, int n0, uint32_t sb, float acc[4][4][4])
{
    const int tid  = threadIdx.x;
    const int lane = tid & 31;
    const int wid  = tid >> 5;
    const int wm   = (wid >> 2) * 64;
    const int wn   = (wid & 3) * 32;

    // cp.async: thread -> row (tid>>1), 4 consecutive 16B chunks (64B)
    const int row = tid >> 1;
    const int c4  = (tid & 1) * 4;
    uint32_t soff[4];
    #pragma unroll
    for (int j = 0; j < 4; j++) {
        const int c = c4 + j;
        soff[j] = row * 128 + ((c ^ (row & 7)) * 16);
    }
    const __half* Agp = A  + (size_t)(m0 + row) * K + c4 * 8;
    const __half* Bgp = Bm + (size_t)(n0 + row) * K + c4 * 8;

    // ldmatrix lane geometry
    const int rowadd = (lane & 7) + ((lane >> 3) & 1) * 8;
    const int swz    = rowadd & 7;
    const int cbit   = lane >> 4;

    const int NIT = K >> 6;
    #pragma unroll
    for (int s = 0; s < 2; s++) {
        const uint32_t st = sb + s * STG_T;
        const int k0 = s << 6;
        #pragma unroll
        for (int j = 0; j < 4; j++) cpa16(st + soff[j], Agp + k0 + j * 8);
        #pragma unroll
        for (int j = 0; j < 4; j++) cpa16(st + STG_OP + soff[j], Bgp + k0 + j * 8);
        CP_COMMIT();
    }
    CP_WAIT1();
    __syncthreads();

    int s = 0;
    for (int it = 0; it < NIT; it++) {
        const uint32_t bA = sb + s * STG_T;
        const uint32_t bB = bA + STG_OP;
        #pragma unroll
        for (int kb = 0; kb < 4; kb++) {
            const uint32_t choff = (uint32_t)((((kb << 1) + cbit) ^ swz) * 16);
            const uint32_t aaddr = bA + (wm + rowadd) * 128 + choff;
            const uint32_t baddr = bB + (wn + rowadd) * 128 + choff;
            uint32_t af[4][4], br[2][4];
            #pragma unroll
            for (int mf = 0; mf < 4; mf++)
                LDSM4(af[mf][0], af[mf][1], af[mf][2], af[mf][3], aaddr + mf * 2048);
            #pragma unroll
            for (int nb = 0; nb < 2; nb++)
                LDSM4(br[nb][0], br[nb][1], br[nb][2], br[nb][3], baddr + nb * 2048);
            #pragma unroll
            for (int mf = 0; mf < 4; mf++) {
                #pragma unroll
                for (int nf = 0; nf < 4; nf++) {
                    uint32_t b2[2] = { br[nf >> 1][nf & 1], br[nf >> 1][(nf & 1) + 2] };
                    mma16(acc[mf][nf], af[mf], b2);
                }
            }
        }
        if (it + 2 < NIT) {
            int sp = s + 2; if (sp >= 3) sp -= 3;
            const uint32_t st = sb + sp * STG_T;
            const int k0 = (it + 2) << 6;
            #pragma unroll
            for (int j = 0; j < 4; j++) cpa16(st + soff[j], Agp + k0 + j * 8);
            #pragma unroll
            for (int j = 0; j < 4; j++) cpa16(st + STG_OP + soff[j], Bgp + k0 + j * 8);
        }
        CP_COMMIT();
        CP_WAIT1();
        __syncthreads();
        if (++s == 3) s = 0;
    }
}

#define EPI_NONE 0
#define EPI_TANH 1
#define EPI_W    2
#define EPI_SIG  3
#define EPI_VMIX 4

__device__ __forceinline__ void zero_acc(float acc[4][4][4]) {
    #pragma unroll
    for (int i = 0; i < 4; i++)
        #pragma unroll
        for (int j = 0; j < 4; j++)
            #pragma unroll
            for (int q = 0; q < 4; q++) acc[i][j][q] = 0.0f;
}

// ---------------- merged K=2048 GEMMs: big-3 (3072 CTAs) + LoRA stage-1 (320) --
__global__ __launch_bounds__(256, 2) void gemm_k2048(float* __restrict__ out_r)
{
    extern __shared__ __half smraw[];
    const uint32_t sb = smem_u32(smraw);
    const int bid = blockIdx.x;

    const __half* A;
    const __half* Wp;
    float* Of = nullptr;
    __half* Oh = nullptr;
    int m0, n0 = 0, Nst, epi = EPI_NONE;

    if (bid < 3072) {
        const int g = bid >> 10, rem = bid & 1023;
        m0 = (rem >> 4) * 128;
        n0 = (rem & 15) * 128;
        A  = (g == 0) ? g_xr : (g == 1) ? g_xk : g_xv;
        Wp = (g == 0) ? g_wr : (g == 1) ? g_wk : g_wv;
        Of = (g == 0) ? out_r : (g == 1) ? g_ko : g_vg;
        Nst = 2048;
    } else {
        const int sid = bid - 3072;
        const int job = sid >> 6;
        m0 = (sid & 63) * 128;
        if (job == 0)      { A = g_xw; Wp = g_w1p; Oh = g_hw; Nst = 128; epi = EPI_TANH; }
        else if (job == 1) { A = g_xa; Wp = g_a1p; Oh = g_ha; Nst = 128; }
        else if (job == 2) { A = g_xv; Wp = g_v1p; Oh = g_hv; Nst = 128; }
        else               { A = g_xg; Wp = g_g1p; Oh = g_hg; Nst = 256; epi = EPI_SIG;
                             n0 = (job == 4) ? 128 : 0; }
    }

    float acc[4][4][4];
    zero_acc(acc);
    mainloop64(A, Wp, Cdim, m0, n0, sb, acc);

    const int lane = threadIdx.x & 31;
    const int wid  = threadIdx.x >> 5;
    const int wm = (wid >> 2) * 64, wn = (wid & 3) * 32;
    const int tq = lane >> 2, tr = lane & 3;

    if (Of) {
        #pragma unroll
        for (int mf = 0; mf < 4; mf++) {
            #pragma unroll
            for (int nf = 0; nf < 4; nf++) {
                const int n = n0 + wn + nf * 8 + tr * 2;
                #pragma unroll
                for (int h = 0; h < 2; h++) {
                    const int m = m0 + wm + mf * 16 + tq + h * 8;
                    *(float2*)&Of[(size_t)m * 2048 + n] =
                        make_float2(acc[mf][nf][h * 2], acc[mf][nf][h * 2 + 1]);
                }
            }
        }
    } else {
        #pragma unroll
        for (int mf = 0; mf < 4; mf++) {
            #pragma unroll
            for (int nf = 0; nf < 4; nf++) {
                const int n = n0 + wn + nf * 8 + tr * 2;
                #pragma unroll
                for (int h = 0; h < 2; h++) {
                    const int m = m0 + wm + mf * 16 + tq + h * 8;
                    float o0 = acc[mf][nf][h * 2], o1 = acc[mf][nf][h * 2 + 1];
                    if (epi == EPI_TANH)     { o0 = tanhf(o0); o1 = tanhf(o1); }
                    else if (epi == EPI_SIG) { o0 = sigmoidf_(o0); o1 = sigmoidf_(o1); }
                    *(__half2*)&Oh[(size_t)m * Nst + n] = __floats2half2_rn(o0, o1);
                }
            }
        }
    }
}

// ---------------- LoRA stage-2 (z-merged, fused epilogues) ----------------
__global__ __launch_bounds__(256, 2) void gemm_s2(
    float* __restrict__ out_w, float* __restrict__ out_a,
    float* __restrict__ out_v, float* __restrict__ out_g,
    const float* __restrict__ w0, const float* __restrict__ a0,
    const float* __restrict__ v0, const float* __restrict__ vfp)
{
    extern __shared__ __half smraw[];
    const uint32_t sb = smem_u32(smraw);
    const int z = blockIdx.z;
    const __half* A;
    const __half* Wp;
    float* O;
    const float* bias = nullptr;
    int K, epi;
    if (z == 0)      { A = g_hw; Wp = g_w2p; O = out_w; K = 128; epi = EPI_W;    bias = w0; }
    else if (z == 1) { A = g_ha; Wp = g_a2p; O = out_a; K = 128; epi = EPI_SIG;  bias = a0; }
    else if (z == 2) { A = g_hv; Wp = g_v2p; O = out_v; K = 128; epi = EPI_VMIX; bias = v0; }
    else             { A = g_hg; Wp = g_g2p; O = out_g; K = 256; epi = EPI_NONE; }

    const int n0 = blockIdx.x * 128;
    const int m0 = blockIdx.y * 128;
    float acc[4][4][4];
    zero_acc(acc);
    mainloop64(A, Wp, K, m0, n0, sb, acc);

    const int lane = threadIdx.x & 31;
    const int wid  = threadIdx.x >> 5;
    const int wm = (wid >> 2) * 64, wn = (wid & 3) * 32;
    const int tq = lane >> 2, tr = lane & 3;
    #pragma unroll
    for (int mf = 0; mf < 4; mf++) {
        #pragma unroll
        for (int nf = 0; nf < 4; nf++) {
            const int n = n0 + wn + nf * 8 + tr * 2;
            float bv0 = 0.0f, bv1 = 0.0f;
            if (bias) { bv0 = bias[n]; bv1 = bias[n + 1]; }
            #pragma unroll
            for (int h = 0; h < 2; h++) {
                const int m = m0 + wm + mf * 16 + tq + h * 8;
                float v0c = acc[mf][nf][h * 2], v1c = acc[mf][nf][h * 2 + 1];
                float o0, o1;
                if (epi == EPI_W) {
                    float y0 = bv0 + v0c, y1 = bv1 + v1c;
                    o0 = -(fmaxf(-y0, 0.0f) + log1pf(expf(-fabsf(y0)))) - 0.5f;
                    o1 = -(fmaxf(-y1, 0.0f) + log1pf(expf(-fabsf(y1)))) - 0.5f;
                } else if (epi == EPI_SIG) {
                    o0 = sigmoidf_(v0c + bv0); o1 = sigmoidf_(v1c + bv1);
                } else if (epi == EPI_VMIX) {
                    float s0 = sigmoidf_(bv0 + v0c), s1 = sigmoidf_(bv1 + v1c);
                    size_t ix = (size_t)m * Cdim + n;
                    float vg0 = g_vg[ix], vg1 = g_vg[ix + 1];
                    o0 = vg0 + (vfp[ix] - vg0) * s0;
                    o1 = vg1 + (vfp[ix + 1] - vg1) * s1;
                } else { o0 = v0c; o1 = v1c; }
                *(float2*)&O[(size_t)m * Cdim + n] = make_float2(o0, o1);
            }
        }
    }
}

// ---------------- elementwise producers (vectorized) ----------------
__global__ __launch_bounds__(256) void mix_kernel(
    const float* __restrict__ x, const float* __restrict__ vf,
    const float* __restrict__ mr, const float* __restrict__ mw,
    const float* __restrict__ mk, const float* __restrict__ mv,
    const float* __restrict__ ma, const float* __restrict__ mg,
    float* __restrict__ out_vf)
{
    size_t i4 = (size_t)blockIdx.x * blockDim.x + threadIdx.x;
    if (i4 >= BTC / 4) return;
    size_t idx = i4 * 4;
    int c   = (int)(idx & (Cdim - 1));
    int row = (int)(idx >> 11);
    int t   = row & (Tdim - 1);
    float4 xc = *(const float4*)&x[idx];
    float4 xp = (t == 0) ? make_float4(0.f, 0.f, 0.f, 0.f) : *(const float4*)&x[idx - Cdim];
    float4 xx = make_float4(xp.x - xc.x, xp.y - xc.y, xp.z - xc.z, xp.w - xc.w);
    *(float4*)&out_vf[idx] = *(const float4*)&vf[idx];
    #define DOMIX(dst, mm) do { \
        float4 mv_ = *(const float4*)&mm[c]; \
        __half2 h0_ = __floats2half2_rn(fmaf(xx.x, mv_.x, xc.x), fmaf(xx.y, mv_.y, xc.y)); \
        __half2 h1_ = __floats2half2_rn(fmaf(xx.z, mv_.z, xc.z), fmaf(xx.w, mv_.w, xc.w)); \
        uint2 u_; u_.x = *(uint32_t*)&h0_; u_.y = *(uint32_t*)&h1_; \
        *(uint2*)&dst[idx] = u_; \
    } while (0)
    DOMIX(g_xr, mr); DOMIX(g_xw, mw); DOMIX(g_xk, mk);
    DOMIX(g_xv, mv); DOMIX(g_xa, ma); DOMIX(g_xg, mg);
    #undef DOMIX
}

__global__ __launch_bounds__(256) void prep_big(
    const float* __restrict__ Wr, const float* __restrict__ Wk, const float* __restrict__ Wv)
{
    size_t i4 = (size_t)blockIdx.x * blockDim.x + threadIdx.x;
    if (i4 >= (size_t)Cdim * Cdim / 4) return;
    size_t idx = i4 * 4;
    int z = blockIdx.z;
    const float* W = (z == 0) ? Wr : (z == 1) ? Wk : Wv;
    __half* P = (z == 0) ? g_wr : (z == 1) ? g_wk : g_wv;
    float4 wv = *(const float4*)&W[idx];
    __half2 h0 = __floats2half2_rn(wv.x, wv.y);
    __half2 h1 = __floats2half2_rn(wv.z, wv.w);
    uint2 u; u.x = *(uint32_t*)&h0; u.y = *(uint32_t*)&h1;
    *(uint2*)&P[idx] = u;
}

// LoRA prep stage-1 weights, z-batched: [C,D] -> [Dp,C] half padded
__global__ __launch_bounds__(256) void prep_l1_all(
    const float* __restrict__ w1, const float* __restrict__ a1,
    const float* __restrict__ v1, const float* __restrict__ g1)
{
    const int z = blockIdx.z;
    const float* src = (z == 0) ? w1 : (z == 1) ? a1 : (z == 2) ? v1 : g1;
    __half* dst = (z == 0) ? g_w1p : (z == 1) ? g_a1p : (z == 2) ? g_v1p : g_g1p;
    const int D_ = (z == 0) ? 128 : (z == 1) ? 128 : (z == 2) ? 64 : 224;
    const int Dp = (z == 3) ? 256 : 128;
    size_t idx = (size_t)blockIdx.x * blockDim.x + threadIdx.x;
    if (idx >= (size_t)Dp * Cdim) return;
    int nn = (int)(idx / Cdim), k = (int)(idx % Cdim);
    dst[idx] = __float2half((nn < D_) ? src[(size_t)k * D_ + nn] : 0.0f);
}

// LoRA prep stage-2 weights, z-batched: [D,C] -> [C,Dp] half padded
__global__ __launch_bounds__(256) void prep_l2_all(
    const float* __restrict__ w2, const float* __restrict__ a2,
    const float* __restrict__ v2, const float* __restrict__ g2)
{
    const int z = blockIdx.z;
    const float* src = (z == 0) ? w2 : (z == 1) ? a2 : (z == 2) ? v2 : g2;
    __half* dst = (z == 0) ? g_w2p : (z == 1) ? g_a2p : (z == 2) ? g_v2p : g_g2p;
    const int D_ = (z == 0) ? 128 : (z == 1) ? 128 : (z == 2) ? 64 : 224;
    const int Dp = (z == 3) ? 256 : 128;
    size_t idx = (size_t)blockIdx.x * blockDim.x + threadIdx.x;
    if (idx >= (size_t)Cdim * Dp) return;
    int nn = (int)(idx / Dp), d = (int)(idx % Dp);
    dst[idx] = __float2half((d < D_) ? src[(size_t)d * Cdim + nn] : 0.0f);
}

// ---------------- kk / final k ----------------
__global__ __launch_bounds__(256) void kk_fin_kernel(
    const float* __restrict__ k_k, const float* __restrict__ k_a,
    const float* __restrict__ a_out,
    float* __restrict__ out_kk, float* __restrict__ out_k)
{
    int gw   = (blockIdx.x * blockDim.x + threadIdx.x) >> 5;
    int lane = threadIdx.x & 31;
    int row  = gw >> 5;
    int h    = gw & 31;
    if (row >= Mrows) return;
    int bse = row * Cdim + h * HSZ;
    int c0 = h * HSZ + lane, c1 = c0 + 32;
    float k0v = g_ko[bse + lane];
    float k1v = g_ko[bse + 32 + lane];
    float kk0 = k0v * k_k[c0];
    float kk1 = k1v * k_k[c1];
    float ss = kk0 * kk0 + kk1 * kk1;
    #pragma unroll
    for (int o = 16; o > 0; o >>= 1) ss += __shfl_xor_sync(0xFFFFFFFFu, ss, o);
    float inv = 1.0f / fmaxf(sqrtf(ss), 1e-12f);
    out_kk[bse + lane]      = kk0 * inv;
    out_kk[bse + 32 + lane] = kk1 * inv;
    float a0v = a_out[bse + lane];
    float a1v = a_out[bse + 32 + lane];
    out_k[bse + lane]      = k0v * fmaf(a0v - 1.0f, k_a[c0], 1.0f);
    out_k[bse + 32 + lane] = k1v * fmaf(a1v - 1.0f, k_a[c1], 1.0f);
}

// ---------------- launch ----------------
extern "C" void kernel_launch(void* const* d_in, const int* in_sizes, int n_in,
                              void* d_out, int out_size)
{
    const float* x   = (const float*)d_in[0];
    const float* vf  = (const float*)d_in[1];
    const float* x_r = (const float*)d_in[2];
    const float* x_w = (const float*)d_in[3];
    const float* x_k = (const float*)d_in[4];
    const float* x_v = (const float*)d_in[5];
    const float* x_a = (const float*)d_in[6];
    const float* x_g = (const float*)d_in[7];
    const float* w0  = (const float*)d_in[8];
    const float* w1  = (const float*)d_in[9];
    const float* w2  = (const float*)d_in[10];
    const float* a0  = (const float*)d_in[11];
    const float* a1  = (const float*)d_in[12];
    const float* a2  = (const float*)d_in[13];
    const float* v0  = (const float*)d_in[14];
    const float* v1  = (const float*)d_in[15];
    const float* v2  = (const float*)d_in[16];
    const float* g1  = (const float*)d_in[17];
    const float* g2  = (const float*)d_in[18];
    const float* k_k = (const float*)d_in[19];
    const float* k_a = (const float*)d_in[20];
    const float* Wr  = (const float*)d_in[21];
    const float* Wk  = (const float*)d_in[22];
    const float* Wv  = (const float*)d_in[23];
    (void)in_sizes; (void)n_in; (void)out_size;

    float* out = (float*)d_out;
    float* out_r  = out + 0 * BTC;
    float* out_w  = out + 1 * BTC;
    float* out_k  = out + 2 * BTC;
    float* out_v  = out + 3 * BTC;
    float* out_a  = out + 4 * BTC;
    float* out_g  = out + 5 * BTC;
    float* out_kk = out + 6 * BTC;
    float* out_vf = out + 7 * BTC;

    cudaFuncSetAttribute(gemm_k2048, cudaFuncAttributeMaxDynamicSharedMemorySize, SMEM_TOT);
    cudaFuncSetAttribute(gemm_s2,    cudaFuncAttributeMaxDynamicSharedMemorySize, SMEM_TOT);

    // 1. mix (fp16 activations, vectorized) + vf copy
    mix_kernel<<<(int)((BTC / 4 + 255) / 256), 256>>>(x, vf, x_r, x_w, x_k, x_v, x_a, x_g, out_vf);

    // 2. weight preps (z-batched)
    prep_big<<<dim3((unsigned)(((size_t)Cdim * Cdim / 4 + 255) / 256), 1, 3), 256>>>(Wr, Wk, Wv);
    prep_l1_all<<<dim3((unsigned)((256 * Cdim + 255) / 256), 1, 4), 256>>>(w1, a1, v1, g1);
    prep_l2_all<<<dim3((unsigned)(((size_t)Cdim * 256 + 255) / 256), 1, 4), 256>>>(w2, a2, v2, g2);

    // 3. all K=2048 GEMMs: big-3 + LoRA stage-1, one flat launch
    gemm_k2048<<<3392, 256, SMEM_TOT>>>(out_r);

    // 4. LoRA stage 2 (merged, fused epilogues)
    gemm_s2<<<dim3(Cdim / 128, Mrows / 128, 4), 256, SMEM_TOT>>>(out_w, out_a, out_v, out_g, w0, a0, v0, vf);

    // 5. kk normalize + final k
    kk_fin_kernel<<<Mrows * 32 * 32 / 256, 256>>>(k_k, k_a, out_a, out_kk, out_k);
}

// round 11
// speedup vs baseline: 1.1522x; 1.1522x over previous
#include <cuda_runtime.h>
#include <cuda_fp16.h>
#include <math.h>
#include <stdint.h>

#define Bdim 2
#define Tdim 4096
#define Cdim 2048
#define HSZ  64
#define Mrows 8192
static const size_t BTC = (size_t)Mrows * Cdim;

// ---------------- scratch ----------------
__device__ __half g_xr[(size_t)Mrows * Cdim];
__device__ __half g_xw[(size_t)Mrows * Cdim];
__device__ __half g_xk[(size_t)Mrows * Cdim];
__device__ __half g_xv[(size_t)Mrows * Cdim];
__device__ __half g_xa[(size_t)Mrows * Cdim];
__device__ __half g_xg[(size_t)Mrows * Cdim];
__device__ __half g_wr[(size_t)Cdim * Cdim];
__device__ __half g_wk[(size_t)Cdim * Cdim];
__device__ __half g_wv[(size_t)Cdim * Cdim];
__device__ __half g_w1p[(size_t)128 * Cdim];
__device__ __half g_a1p[(size_t)128 * Cdim];
__device__ __half g_v1p[(size_t)128 * Cdim];
__device__ __half g_g1p[(size_t)256 * Cdim];
__device__ __half g_w2p[(size_t)Cdim * 128];
__device__ __half g_a2p[(size_t)Cdim * 128];
__device__ __half g_v2p[(size_t)Cdim * 128];
__device__ __half g_g2p[(size_t)Cdim * 256];
__device__ __half g_hw[(size_t)Mrows * 128];
__device__ __half g_ha[(size_t)Mrows * 128];
__device__ __half g_hv[(size_t)Mrows * 128];
__device__ __half g_hg[(size_t)Mrows * 256];
__device__ float  g_ko[(size_t)Mrows * Cdim];
__device__ float  g_vg[(size_t)Mrows * Cdim];

// ---------------- helpers ----------------
__device__ __forceinline__ float sigmoidf_(float y) { return 1.0f / (1.0f + expf(-y)); }

__device__ __forceinline__ uint32_t smem_u32(const void* p) {
    uint32_t a;
    asm("{ .reg .u64 t; cvta.to.shared.u64 t, %1; cvt.u32.u64 %0, t; }" : "=r"(a) : "l"(p));
    return a;
}
__device__ __forceinline__ void mma16(float* d, const uint32_t* a, const uint32_t* b) {
    asm volatile("mma.sync.aligned.m16n8k16.row.col.f32.f16.f16.f32 "
        "{%0,%1,%2,%3}, {%4,%5,%6,%7}, {%8,%9}, {%0,%1,%2,%3};"
        : "+f"(d[0]), "+f"(d[1]), "+f"(d[2]), "+f"(d[3])
        : "r"(a[0]), "r"(a[1]), "r"(a[2]), "r"(a[3]), "r"(b[0]), "r"(b[1]));
}
__device__ __forceinline__ void cpa16(uint32_t dst, const __half* src) {
    asm volatile("cp.async.cg.shared.global [%0], [%1], 16;"
        :: "r"(dst), "l"(__cvta_generic_to_global(src)));
}
#define CP_COMMIT() asm volatile("cp.async.commit_group;" ::: "memory")
#define CP_WAIT2()  asm volatile("cp.async.wait_group 2;" ::: "memory")
#define LDSM4(r0,r1,r2,r3,addr) \
    asm volatile("ldmatrix.sync.aligned.m8n8.x4.shared.b16 {%0,%1,%2,%3}, [%4];" \
        : "=r"(r0), "=r"(r1), "=r"(r2), "=r"(r3) : "r"(addr))

// stage size: 128 rows x 32 halves = 8192 bytes per operand; 4 stages
#define STGB 8192
#define NSTG 4

// ---------------- mainloop: 128x128 tile, KC=32, 4-stage cp.async, ldmatrix ----
__device__ __forceinline__ void mainloop(
    const __half* __restrict__ A, const __half* __restrict__ Bm,
    int K, int m0, int n0, uint32_t sA, uint32_t sB, float acc[4][4][4])
{
    const int tid  = threadIdx.x;
    const int lane = tid & 31;
    const int wid  = tid >> 5;
    const int wm   = (wid >> 2) * 64;
    const int wn   = (wid & 3) * 32;

    const int rA  = tid >> 2;
    const int cA  = tid & 3;
    const int rA2 = rA + 64;
    const uint32_t o0 = rA  * 64 + ((cA ^ ((rA  >> 1) & 3)) * 16);
    const uint32_t o1 = rA2 * 64 + ((cA ^ ((rA2 >> 1) & 3)) * 16);
    const __half* Ag0 = A  + (size_t)(m0 + rA)  * K + cA * 8;
    const __half* Ag1 = A  + (size_t)(m0 + rA2) * K + cA * 8;
    const __half* Bg0 = Bm + (size_t)(n0 + rA)  * K + cA * 8;
    const __half* Bg1 = Bm + (size_t)(n0 + rA2) * K + cA * 8;

    const int rowadd = (lane & 7) + ((lane >> 3) & 1) * 8;
    const int swz    = (rowadd >> 1) & 3;
    const int cbit   = lane >> 4;

    const int NIT = K >> 5;
    #pragma unroll
    for (int s = 0; s < 3; s++) {
        const int k0 = s << 5;
        cpa16(sA + s * STGB + o0, Ag0 + k0);
        cpa16(sA + s * STGB + o1, Ag1 + k0);
        cpa16(sB + s * STGB + o0, Bg0 + k0);
        cpa16(sB + s * STGB + o1, Bg1 + k0);
        CP_COMMIT();
    }
    CP_WAIT2();
    __syncthreads();

    int s = 0;
    for (int it = 0; it < NIT; it++) {
        const uint32_t bA = sA + s * STGB;
        const uint32_t bB = sB + s * STGB;
        #pragma unroll
        for (int kb = 0; kb < 2; kb++) {
            const uint32_t choff = (uint32_t)((((kb << 1) + cbit) ^ swz) * 16);
            const uint32_t aaddr = bA + (wm + rowadd) * 64 + choff;
            const uint32_t baddr = bB + (wn + rowadd) * 64 + choff;
            uint32_t af[4][4], br[2][4];
            #pragma unroll
            for (int mf = 0; mf < 4; mf++)
                LDSM4(af[mf][0], af[mf][1], af[mf][2], af[mf][3], aaddr + mf * 1024);
            #pragma unroll
            for (int nb = 0; nb < 2; nb++)
                LDSM4(br[nb][0], br[nb][1], br[nb][2], br[nb][3], baddr + nb * 1024);
            #pragma unroll
            for (int mf = 0; mf < 4; mf++) {
                #pragma unroll
                for (int nf = 0; nf < 4; nf++) {
                    uint32_t b2[2] = { br[nf >> 1][nf & 1], br[nf >> 1][(nf & 1) + 2] };
                    mma16(acc[mf][nf], af[mf], b2);
                }
            }
        }
        if (it + 3 < NIT) {
            int s2 = s + 3; if (s2 >= NSTG) s2 -= NSTG;
            const int k0 = (it + 3) << 5;
            cpa16(sA + s2 * STGB + o0, Ag0 + k0);
            cpa16(sA + s2 * STGB + o1, Ag1 + k0);
            cpa16(sB + s2 * STGB + o0, Bg0 + k0);
            cpa16(sB + s2 * STGB + o1, Bg1 + k0);
        }
        CP_COMMIT();
        CP_WAIT2();
        __syncthreads();
        if (++s == NSTG) s = 0;
    }
}

#define EPI_NONE 0
#define EPI_TANH 1
#define EPI_W    2
#define EPI_SIG  3
#define EPI_VMIX 4

__device__ __forceinline__ void zero_acc(float acc[4][4][4]) {
    #pragma unroll
    for (int i = 0; i < 4; i++)
        #pragma unroll
        for (int j = 0; j < 4; j++)
            #pragma unroll
            for (int q = 0; q < 4; q++) acc[i][j][q] = 0.0f;
}

// ---------------- big-3 GEMMs (z-merged) ----------------
__global__ __launch_bounds__(256, 2) void gemm_big3(float* __restrict__ out_r)
{
    __shared__ __half smA[NSTG * STGB / 2];
    __shared__ __half smB[NSTG * STGB / 2];
    const int z = blockIdx.z;
    const __half* A  = (z == 0) ? g_xr : (z == 1) ? g_xk : g_xv;
    const __half* Wp = (z == 0) ? g_wr : (z == 1) ? g_wk : g_wv;
    float* O         = (z == 0) ? out_r : (z == 1) ? g_ko : g_vg;

    const int n0 = blockIdx.x * 128;
    const int m0 = blockIdx.y * 128;
    float acc[4][4][4];
    zero_acc(acc);
    mainloop(A, Wp, Cdim, m0, n0, smem_u32(smA), smem_u32(smB), acc);

    const int lane = threadIdx.x & 31;
    const int wid  = threadIdx.x >> 5;
    const int wm = (wid >> 2) * 64, wn = (wid & 3) * 32;
    const int tq = lane >> 2, tr = lane & 3;
    #pragma unroll
    for (int mf = 0; mf < 4; mf++) {
        #pragma unroll
        for (int nf = 0; nf < 4; nf++) {
            const int n = n0 + wn + nf * 8 + tr * 2;
            #pragma unroll
            for (int h = 0; h < 2; h++) {
                const int m = m0 + wm + mf * 16 + tq + h * 8;
                *(float2*)&O[(size_t)m * Cdim + n] =
                    make_float2(acc[mf][nf][h * 2], acc[mf][nf][h * 2 + 1]);
            }
        }
    }
}

// ---------------- LoRA stage-1 (z-merged, half outputs) ----------------
__global__ __launch_bounds__(256, 2) void gemm_s1(void)
{
    __shared__ __half smA[NSTG * STGB / 2];
    __shared__ __half smB[NSTG * STGB / 2];
    const int z = blockIdx.z;
    const __half* A;
    const __half* Wp;
    __half* Oh;
    int N, epi;
    if (z == 0)      { A = g_xw; Wp = g_w1p; Oh = g_hw; N = 128; epi = EPI_TANH; }
    else if (z == 1) { A = g_xa; Wp = g_a1p; Oh = g_ha; N = 128; epi = EPI_NONE; }
    else if (z == 2) { A = g_xv; Wp = g_v1p; Oh = g_hv; N = 128; epi = EPI_NONE; }
    else             { A = g_xg; Wp = g_g1p; Oh = g_hg; N = 256; epi = EPI_SIG; }

    const int n0 = blockIdx.x * 128;
    const int m0 = blockIdx.y * 128;
    if (n0 >= N) return;

    float acc[4][4][4];
    zero_acc(acc);
    mainloop(A, Wp, Cdim, m0, n0, smem_u32(smA), smem_u32(smB), acc);

    const int lane = threadIdx.x & 31;
    const int wid  = threadIdx.x >> 5;
    const int wm = (wid >> 2) * 64, wn = (wid & 3) * 32;
    const int tq = lane >> 2, tr = lane & 3;
    #pragma unroll
    for (int mf = 0; mf < 4; mf++) {
        #pragma unroll
        for (int nf = 0; nf < 4; nf++) {
            const int n = n0 + wn + nf * 8 + tr * 2;
            #pragma unroll
            for (int h = 0; h < 2; h++) {
                const int m = m0 + wm + mf * 16 + tq + h * 8;
                float o0 = acc[mf][nf][h * 2], o1 = acc[mf][nf][h * 2 + 1];
                if (epi == EPI_TANH)     { o0 = tanhf(o0); o1 = tanhf(o1); }
                else if (epi == EPI_SIG) { o0 = sigmoidf_(o0); o1 = sigmoidf_(o1); }
                *(__half2*)&Oh[(size_t)m * N + n] = __floats2half2_rn(o0, o1);
            }
        }
    }
}

// ---------------- LoRA stage-2 (z-merged, fused epilogues) ----------------
__global__ __launch_bounds__(256, 2) void gemm_s2(
    float* __restrict__ out_w, float* __restrict__ out_a,
    float* __restrict__ out_v, float* __restrict__ out_g,
    const float* __restrict__ w0, const float* __restrict__ a0,
    const float* __restrict__ v0, const float* __restrict__ vfp)
{
    __shared__ __half smA[NSTG * STGB / 2];
    __shared__ __half smB[NSTG * STGB / 2];
    const int z = blockIdx.z;
    const __half* A;
    const __half* Wp;
    float* O;
    const float* bias = nullptr;
    int K, epi;
    if (z == 0)      { A = g_hw; Wp = g_w2p; O = out_w; K = 128; epi = EPI_W;    bias = w0; }
    else if (z == 1) { A = g_ha; Wp = g_a2p; O = out_a; K = 128; epi = EPI_SIG;  bias = a0; }
    else if (z == 2) { A = g_hv; Wp = g_v2p; O = out_v; K = 128; epi = EPI_VMIX; bias = v0; }
    else             { A = g_hg; Wp = g_g2p; O = out_g; K = 256; epi = EPI_NONE; }

    const int n0 = blockIdx.x * 128;
    const int m0 = blockIdx.y * 128;
    float acc[4][4][4];
    zero_acc(acc);
    mainloop(A, Wp, K, m0, n0, smem_u32(smA), smem_u32(smB), acc);

    const int lane = threadIdx.x & 31;
    const int wid  = threadIdx.x >> 5;
    const int wm = (wid >> 2) * 64, wn = (wid & 3) * 32;
    const int tq = lane >> 2, tr = lane & 3;
    #pragma unroll
    for (int mf = 0; mf < 4; mf++) {
        #pragma unroll
        for (int nf = 0; nf < 4; nf++) {
            const int n = n0 + wn + nf * 8 + tr * 2;
            float bv0 = 0.0f, bv1 = 0.0f;
            if (bias) { bv0 = bias[n]; bv1 = bias[n + 1]; }
            #pragma unroll
            for (int h = 0; h < 2; h++) {
                const int m = m0 + wm + mf * 16 + tq + h * 8;
                float v0c = acc[mf][nf][h * 2], v1c = acc[mf][nf][h * 2 + 1];
                float o0, o1;
                if (epi == EPI_W) {
                    float y0 = bv0 + v0c, y1 = bv1 + v1c;
                    o0 = -(fmaxf(-y0, 0.0f) + log1pf(expf(-fabsf(y0)))) - 0.5f;
                    o1 = -(fmaxf(-y1, 0.0f) + log1pf(expf(-fabsf(y1)))) - 0.5f;
                } else if (epi == EPI_SIG) {
                    o0 = sigmoidf_(v0c + bv0); o1 = sigmoidf_(v1c + bv1);
                } else if (epi == EPI_VMIX) {
                    float s0 = sigmoidf_(bv0 + v0c), s1 = sigmoidf_(bv1 + v1c);
                    size_t ix = (size_t)m * Cdim + n;
                    float vg0 = g_vg[ix], vg1 = g_vg[ix + 1];
                    o0 = vg0 + (vfp[ix] - vg0) * s0;
                    o1 = vg1 + (vfp[ix + 1] - vg1) * s1;
                } else { o0 = v0c; o1 = v1c; }
                *(float2*)&O[(size_t)m * Cdim + n] = make_float2(o0, o1);
            }
        }
    }
}

// ---------------- elementwise producers (vectorized) ----------------
__global__ __launch_bounds__(256) void mix_kernel(
    const float* __restrict__ x, const float* __restrict__ vf,
    const float* __restrict__ mr, const float* __restrict__ mw,
    const float* __restrict__ mk, const float* __restrict__ mv,
    const float* __restrict__ ma, const float* __restrict__ mg,
    float* __restrict__ out_vf)
{
    size_t i4 = (size_t)blockIdx.x * blockDim.x + threadIdx.x;
    if (i4 >= BTC / 4) return;
    size_t idx = i4 * 4;
    int c   = (int)(idx & (Cdim - 1));
    int row = (int)(idx >> 11);
    int t   = row & (Tdim - 1);
    float4 xc = *(const float4*)&x[idx];
    float4 xp = (t == 0) ? make_float4(0.f, 0.f, 0.f, 0.f) : *(const float4*)&x[idx - Cdim];
    float4 xx = make_float4(xp.x - xc.x, xp.y - xc.y, xp.z - xc.z, xp.w - xc.w);
    *(float4*)&out_vf[idx] = *(const float4*)&vf[idx];
    #define DOMIX(dst, mm) do { \
        float4 mv_ = *(const float4*)&mm[c]; \
        __half2 h0_ = __floats2half2_rn(fmaf(xx.x, mv_.x, xc.x), fmaf(xx.y, mv_.y, xc.y)); \
        __half2 h1_ = __floats2half2_rn(fmaf(xx.z, mv_.z, xc.z), fmaf(xx.w, mv_.w, xc.w)); \
        uint2 u_; u_.x = *(uint32_t*)&h0_; u_.y = *(uint32_t*)&h1_; \
        *(uint2*)&dst[idx] = u_; \
    } while (0)
    DOMIX(g_xr, mr); DOMIX(g_xw, mw); DOMIX(g_xk, mk);
    DOMIX(g_xv, mv); DOMIX(g_xa, ma); DOMIX(g_xg, mg);
    #undef DOMIX
}

__global__ __launch_bounds__(256) void prep_big(
    const float* __restrict__ Wr, const float* __restrict__ Wk, const float* __restrict__ Wv)
{
    size_t i4 = (size_t)blockIdx.x * blockDim.x + threadIdx.x;
    if (i4 >= (size_t)Cdim * Cdim / 4) return;
    size_t idx = i4 * 4;
    int z = blockIdx.z;
    const float* W = (z == 0) ? Wr : (z == 1) ? Wk : Wv;
    __half* P = (z == 0) ? g_wr : (z == 1) ? g_wk : g_wv;
    float4 wv = *(const float4*)&W[idx];
    __half2 h0 = __floats2half2_rn(wv.x, wv.y);
    __half2 h1 = __floats2half2_rn(wv.z, wv.w);
    uint2 u; u.x = *(uint32_t*)&h0; u.y = *(uint32_t*)&h1;
    *(uint2*)&P[idx] = u;
}

// LoRA prep stage-1 weights, z-batched: [C,D] -> [Dp,C] half padded
__global__ __launch_bounds__(256) void prep_l1_all(
    const float* __restrict__ w1, const float* __restrict__ a1,
    const float* __restrict__ v1, const float* __restrict__ g1)
{
    const int z = blockIdx.z;
    const float* src = (z == 0) ? w1 : (z == 1) ? a1 : (z == 2) ? v1 : g1;
    __half* dst = (z == 0) ? g_w1p : (z == 1) ? g_a1p : (z == 2) ? g_v1p : g_g1p;
    const int D_ = (z == 0) ? 128 : (z == 1) ? 128 : (z == 2) ? 64 : 224;
    const int Dp = (z == 3) ? 256 : 128;
    size_t idx = (size_t)blockIdx.x * blockDim.x + threadIdx.x;
    if (idx >= (size_t)Dp * Cdim) return;
    int nn = (int)(idx / Cdim), k = (int)(idx % Cdim);
    dst[idx] = __float2half((nn < D_) ? src[(size_t)k * D_ + nn] : 0.0f);
}

// LoRA prep stage-2 weights, z-batched: [D,C] -> [C,Dp] half padded
__global__ __launch_bounds__(256) void prep_l2_all(
    const float* __restrict__ w2, const float* __restrict__ a2,
    const float* __restrict__ v2, const float* __restrict__ g2)
{
    const int z = blockIdx.z;
    const float* src = (z == 0) ? w2 : (z == 1) ? a2 : (z == 2) ? v2 : g2;
    __half* dst = (z == 0) ? g_w2p : (z == 1) ? g_a2p : (z == 2) ? g_v2p : g_g2p;
    const int D_ = (z == 0) ? 128 : (z == 1) ? 128 : (z == 2) ? 64 : 224;
    const int Dp = (z == 3) ? 256 : 128;
    size_t idx = (size_t)blockIdx.x * blockDim.x + threadIdx.x;
    if (idx >= (size_t)Cdim * Dp) return;
    int nn = (int)(idx / Dp), d = (int)(idx % Dp);
    dst[idx] = __float2half((d < D_) ? src[(size_t)d * Cdim + nn] : 0.0f);
}

// ---------------- kk / final k ----------------
__global__ __launch_bounds__(256) void kk_fin_kernel(
    const float* __restrict__ k_k, const float* __restrict__ k_a,
    const float* __restrict__ a_out,
    float* __restrict__ out_kk, float* __restrict__ out_k)
{
    int gw   = (blockIdx.x * blockDim.x + threadIdx.x) >> 5;
    int lane = threadIdx.x & 31;
    int row  = gw >> 5;
    int h    = gw & 31;
    if (row >= Mrows) return;
    int bse = row * Cdim + h * HSZ;
    int c0 = h * HSZ + lane, c1 = c0 + 32;
    float k0v = g_ko[bse + lane];
    float k1v = g_ko[bse + 32 + lane];
    float kk0 = k0v * k_k[c0];
    float kk1 = k1v * k_k[c1];
    float ss = kk0 * kk0 + kk1 * kk1;
    #pragma unroll
    for (int o = 16; o > 0; o >>= 1) ss += __shfl_xor_sync(0xFFFFFFFFu, ss, o);
    float inv = 1.0f / fmaxf(sqrtf(ss), 1e-12f);
    out_kk[bse + lane]      = kk0 * inv;
    out_kk[bse + 32 + lane] = kk1 * inv;
    float a0v = a_out[bse + lane];
    float a1v = a_out[bse + 32 + lane];
    out_k[bse + lane]      = k0v * fmaf(a0v - 1.0f, k_a[c0], 1.0f);
    out_k[bse + 32 + lane] = k1v * fmaf(a1v - 1.0f, k_a[c1], 1.0f);
}

// ---------------- launch ----------------
extern "C" void kernel_launch(void* const* d_in, const int* in_sizes, int n_in,
                              void* d_out, int out_size)
{
    const float* x   = (const float*)d_in[0];
    const float* vf  = (const float*)d_in[1];
    const float* x_r = (const float*)d_in[2];
    const float* x_w = (const float*)d_in[3];
    const float* x_k = (const float*)d_in[4];
    const float* x_v = (const float*)d_in[5];
    const float* x_a = (const float*)d_in[6];
    const float* x_g = (const float*)d_in[7];
    const float* w0  = (const float*)d_in[8];
    const float* w1  = (const float*)d_in[9];
    const float* w2  = (const float*)d_in[10];
    const float* a0  = (const float*)d_in[11];
    const float* a1  = (const float*)d_in[12];
    const float* a2  = (const float*)d_in[13];
    const float* v0  = (const float*)d_in[14];
    const float* v1  = (const float*)d_in[15];
    const float* v2  = (const float*)d_in[16];
    const float* g1  = (const float*)d_in[17];
    const float* g2  = (const float*)d_in[18];
    const float* k_k = (const float*)d_in[19];
    const float* k_a = (const float*)d_in[20];
    const float* Wr  = (const float*)d_in[21];
    const float* Wk  = (const float*)d_in[22];
    const float* Wv  = (const float*)d_in[23];
    (void)in_sizes; (void)n_in; (void)out_size;

    float* out = (float*)d_out;
    float* out_r  = out + 0 * BTC;
    float* out_w  = out + 1 * BTC;
    float* out_k  = out + 2 * BTC;
    float* out_v  = out + 3 * BTC;
    float* out_a  = out + 4 * BTC;
    float* out_g  = out + 5 * BTC;
    float* out_kk = out + 6 * BTC;
    float* out_vf = out + 7 * BTC;

    // 1. mix (fp16 activations, vectorized) + vf copy
    mix_kernel<<<(int)((BTC / 4 + 255) / 256), 256>>>(x, vf, x_r, x_w, x_k, x_v, x_a, x_g, out_vf);

    // 2. weight preps (z-batched)
    prep_big<<<dim3((unsigned)(((size_t)Cdim * Cdim / 4 + 255) / 256), 1, 3), 256>>>(Wr, Wk, Wv);
    prep_l1_all<<<dim3((unsigned)((256 * Cdim + 255) / 256), 1, 4), 256>>>(w1, a1, v1, g1);
    prep_l2_all<<<dim3((unsigned)(((size_t)Cdim * 256 + 255) / 256), 1, 4), 256>>>(w2, a2, v2, g2);

    // 3. big GEMMs (merged, 128x128 tiles, 4-stage, 2 CTA/SM)
    gemm_big3<<<dim3(Cdim / 128, Mrows / 128, 3), 256>>>(out_r);

    // 4. LoRA stage 1 (merged)
    gemm_s1<<<dim3(2, Mrows / 128, 4), 256>>>();

    // 5. LoRA stage 2 (merged, fused epilogues)
    gemm_s2<<<dim3(Cdim / 128, Mrows / 128, 4), 256>>>(out_w, out_a, out_v, out_g, w0, a0, v0, vf);

    // 6. kk normalize + final k
    kk_fin_kernel<<<Mrows * 32 * 32 / 256, 256>>>(k_k, k_a, out_a, out_kk, out_k);
}

// round 12
// speedup vs baseline: 1.1996x; 1.0411x over previous
#include <cuda_runtime.h>
#include <cuda_fp16.h>
#include <math.h>
#include <stdint.h>

#define Bdim 2
#define Tdim 4096
#define Cdim 2048
#define HSZ  64
#define Mrows 8192
static const size_t BTC = (size_t)Mrows * Cdim;

// ---------------- scratch ----------------
__device__ __half g_xr[(size_t)Mrows * Cdim];
__device__ __half g_xw[(size_t)Mrows * Cdim];
__device__ __half g_xk[(size_t)Mrows * Cdim];
__device__ __half g_xv[(size_t)Mrows * Cdim];
__device__ __half g_xa[(size_t)Mrows * Cdim];
__device__ __half g_xg[(size_t)Mrows * Cdim];
__device__ __half g_wr[(size_t)Cdim * Cdim];
__device__ __half g_wk[(size_t)Cdim * Cdim];
__device__ __half g_wv[(size_t)Cdim * Cdim];
__device__ __half g_w1p[(size_t)128 * Cdim];
__device__ __half g_a1p[(size_t)128 * Cdim];
__device__ __half g_v1p[(size_t)128 * Cdim];
__device__ __half g_g1p[(size_t)256 * Cdim];
__device__ __half g_w2p[(size_t)Cdim * 128];
__device__ __half g_a2p[(size_t)Cdim * 128];
__device__ __half g_v2p[(size_t)Cdim * 128];
__device__ __half g_g2p[(size_t)Cdim * 256];
__device__ __half g_hw[(size_t)Mrows * 128];
__device__ __half g_ha[(size_t)Mrows * 128];
__device__ __half g_hv[(size_t)Mrows * 128];
__device__ __half g_hg[(size_t)Mrows * 256];
__device__ float  g_ko[(size_t)Mrows * Cdim];
__device__ float  g_vg[(size_t)Mrows * Cdim];

// ---------------- helpers ----------------
__device__ __forceinline__ float sigmoidf_(float y) { return 1.0f / (1.0f + expf(-y)); }

__device__ __forceinline__ uint32_t smem_u32(const void* p) {
    uint32_t a;
    asm("{ .reg .u64 t; cvta.to.shared.u64 t, %1; cvt.u32.u64 %0, t; }" : "=r"(a) : "l"(p));
    return a;
}
__device__ __forceinline__ void mma16(float* d, const uint32_t* a, const uint32_t* b) {
    asm volatile("mma.sync.aligned.m16n8k16.row.col.f32.f16.f16.f32 "
        "{%0,%1,%2,%3}, {%4,%5,%6,%7}, {%8,%9}, {%0,%1,%2,%3};"
        : "+f"(d[0]), "+f"(d[1]), "+f"(d[2]), "+f"(d[3])
        : "r"(a[0]), "r"(a[1]), "r"(a[2]), "r"(a[3]), "r"(b[0]), "r"(b[1]));
}
__device__ __forceinline__ void cpa16(uint32_t dst, const __half* src) {
    asm volatile("cp.async.cg.shared.global [%0], [%1], 16;"
        :: "r"(dst), "l"(__cvta_generic_to_global(src)));
}
#define CP_COMMIT() asm volatile("cp.async.commit_group;" ::: "memory")
#define CP_WAIT2()  asm volatile("cp.async.wait_group 2;" ::: "memory")
#define LDSM4(r0,r1,r2,r3,addr) \
    asm volatile("ldmatrix.sync.aligned.m8n8.x4.shared.b16 {%0,%1,%2,%3}, [%4];" \
        : "=r"(r0), "=r"(r1), "=r"(r2), "=r"(r3) : "r"(addr))

// stage size: 128 rows x 32 halves = 8192 bytes per operand; 4 stages
#define STGB 8192
#define NSTG 4

// ---------------- mainloop: 128x128 tile, KC=32, 4-stage cp.async, ldmatrix ----
__device__ __forceinline__ void mainloop(
    const __half* __restrict__ A, const __half* __restrict__ Bm,
    int K, int m0, int n0, uint32_t sA, uint32_t sB, float acc[4][4][4])
{
    const int tid  = threadIdx.x;
    const int lane = tid & 31;
    const int wid  = tid >> 5;
    const int wm   = (wid >> 2) * 64;
    const int wn   = (wid & 3) * 32;

    const int rA  = tid >> 2;
    const int cA  = tid & 3;
    const int rA2 = rA + 64;
    const uint32_t o0 = rA  * 64 + ((cA ^ ((rA  >> 1) & 3)) * 16);
    const uint32_t o1 = rA2 * 64 + ((cA ^ ((rA2 >> 1) & 3)) * 16);
    const __half* Ag0 = A  + (size_t)(m0 + rA)  * K + cA * 8;
    const __half* Ag1 = A  + (size_t)(m0 + rA2) * K + cA * 8;
    const __half* Bg0 = Bm + (size_t)(n0 + rA)  * K + cA * 8;
    const __half* Bg1 = Bm + (size_t)(n0 + rA2) * K + cA * 8;

    const int rowadd = (lane & 7) + ((lane >> 3) & 1) * 8;
    const int swz    = (rowadd >> 1) & 3;
    const int cbit   = lane >> 4;

    const int NIT = K >> 5;
    #pragma unroll
    for (int s = 0; s < 3; s++) {
        const int k0 = s << 5;
        cpa16(sA + s * STGB + o0, Ag0 + k0);
        cpa16(sA + s * STGB + o1, Ag1 + k0);
        cpa16(sB + s * STGB + o0, Bg0 + k0);
        cpa16(sB + s * STGB + o1, Bg1 + k0);
        CP_COMMIT();
    }
    CP_WAIT2();
    __syncthreads();

    int s = 0;
    for (int it = 0; it < NIT; it++) {
        const uint32_t bA = sA + s * STGB;
        const uint32_t bB = sB + s * STGB;
        #pragma unroll
        for (int kb = 0; kb < 2; kb++) {
            const uint32_t choff = (uint32_t)((((kb << 1) + cbit) ^ swz) * 16);
            const uint32_t aaddr = bA + (wm + rowadd) * 64 + choff;
            const uint32_t baddr = bB + (wn + rowadd) * 64 + choff;
            uint32_t af[4][4], br[2][4];
            #pragma unroll
            for (int mf = 0; mf < 4; mf++)
                LDSM4(af[mf][0], af[mf][1], af[mf][2], af[mf][3], aaddr + mf * 1024);
            #pragma unroll
            for (int nb = 0; nb < 2; nb++)
                LDSM4(br[nb][0], br[nb][1], br[nb][2], br[nb][3], baddr + nb * 1024);
            #pragma unroll
            for (int mf = 0; mf < 4; mf++) {
                #pragma unroll
                for (int nf = 0; nf < 4; nf++) {
                    uint32_t b2[2] = { br[nf >> 1][nf & 1], br[nf >> 1][(nf & 1) + 2] };
                    mma16(acc[mf][nf], af[mf], b2);
                }
            }
        }
        if (it + 3 < NIT) {
            int s2 = s + 3; if (s2 >= NSTG) s2 -= NSTG;
            const int k0 = (it + 3) << 5;
            cpa16(sA + s2 * STGB + o0, Ag0 + k0);
            cpa16(sA + s2 * STGB + o1, Ag1 + k0);
            cpa16(sB + s2 * STGB + o0, Bg0 + k0);
            cpa16(sB + s2 * STGB + o1, Bg1 + k0);
        }
        CP_COMMIT();
        CP_WAIT2();
        __syncthreads();
        if (++s == NSTG) s = 0;
    }
}

#define EPI_NONE 0
#define EPI_TANH 1
#define EPI_W    2
#define EPI_SIG  3
#define EPI_VMIX 4

__device__ __forceinline__ void zero_acc(float acc[4][4][4]) {
    #pragma unroll
    for (int i = 0; i < 4; i++)
        #pragma unroll
        for (int j = 0; j < 4; j++)
            #pragma unroll
            for (int q = 0; q < 4; q++) acc[i][j][q] = 0.0f;
}

// ---------------- merged K=2048 GEMMs: big-3 (3072 CTAs) + LoRA s1 (320) ------
__global__ __launch_bounds__(256, 2) void gemm_k2048(float* __restrict__ out_r)
{
    __shared__ __half smA[NSTG * STGB / 2];
    __shared__ __half smB[NSTG * STGB / 2];
    const int bid = blockIdx.x;

    const __half* A;
    const __half* Wp;
    float* Of = nullptr;
    __half* Oh = nullptr;
    int m0, n0 = 0, Nst = 2048, epi = EPI_NONE;

    if (bid < 3072) {
        const int g = bid >> 10, rem = bid & 1023;
        m0 = (rem >> 4) * 128;
        n0 = (rem & 15) * 128;
        A  = (g == 0) ? g_xr : (g == 1) ? g_xk : g_xv;
        Wp = (g == 0) ? g_wr : (g == 1) ? g_wk : g_wv;
        Of = (g == 0) ? out_r : (g == 1) ? g_ko : g_vg;
    } else {
        const int sid = bid - 3072;
        const int job = sid >> 6;                 // 0..4
        m0 = (sid & 63) * 128;
        if (job == 0)      { A = g_xw; Wp = g_w1p; Oh = g_hw; Nst = 128; epi = EPI_TANH; }
        else if (job == 1) { A = g_xa; Wp = g_a1p; Oh = g_ha; Nst = 128; }
        else if (job == 2) { A = g_xv; Wp = g_v1p; Oh = g_hv; Nst = 128; }
        else               { A = g_xg; Wp = g_g1p; Oh = g_hg; Nst = 256; epi = EPI_SIG;
                             n0 = (job == 4) ? 128 : 0; }
    }

    float acc[4][4][4];
    zero_acc(acc);
    mainloop(A, Wp, Cdim, m0, n0, smem_u32(smA), smem_u32(smB), acc);

    const int lane = threadIdx.x & 31;
    const int wid  = threadIdx.x >> 5;
    const int wm = (wid >> 2) * 64, wn = (wid & 3) * 32;
    const int tq = lane >> 2, tr = lane & 3;

    if (Of) {
        #pragma unroll
        for (int mf = 0; mf < 4; mf++) {
            #pragma unroll
            for (int nf = 0; nf < 4; nf++) {
                const int n = n0 + wn + nf * 8 + tr * 2;
                #pragma unroll
                for (int h = 0; h < 2; h++) {
                    const int m = m0 + wm + mf * 16 + tq + h * 8;
                    *(float2*)&Of[(size_t)m * 2048 + n] =
                        make_float2(acc[mf][nf][h * 2], acc[mf][nf][h * 2 + 1]);
                }
            }
        }
    } else {
        #pragma unroll
        for (int mf = 0; mf < 4; mf++) {
            #pragma unroll
            for (int nf = 0; nf < 4; nf++) {
                const int n = n0 + wn + nf * 8 + tr * 2;
                #pragma unroll
                for (int h = 0; h < 2; h++) {
                    const int m = m0 + wm + mf * 16 + tq + h * 8;
                    float o0 = acc[mf][nf][h * 2], o1 = acc[mf][nf][h * 2 + 1];
                    if (epi == EPI_TANH)     { o0 = tanhf(o0); o1 = tanhf(o1); }
                    else if (epi == EPI_SIG) { o0 = sigmoidf_(o0); o1 = sigmoidf_(o1); }
                    *(__half2*)&Oh[(size_t)m * Nst + n] = __floats2half2_rn(o0, o1);
                }
            }
        }
    }
}

// ---------------- LoRA stage-2 (z-merged, fused epilogues) ----------------
__global__ __launch_bounds__(256, 2) void gemm_s2(
    float* __restrict__ out_w, float* __restrict__ out_a,
    float* __restrict__ out_v, float* __restrict__ out_g,
    const float* __restrict__ w0, const float* __restrict__ a0,
    const float* __restrict__ v0, const float* __restrict__ vfp)
{
    __shared__ __half smA[NSTG * STGB / 2];
    __shared__ __half smB[NSTG * STGB / 2];
    const int z = blockIdx.z;
    const __half* A;
    const __half* Wp;
    float* O;
    const float* bias = nullptr;
    int K, epi;
    if (z == 0)      { A = g_hw; Wp = g_w2p; O = out_w; K = 128; epi = EPI_W;    bias = w0; }
    else if (z == 1) { A = g_ha; Wp = g_a2p; O = out_a; K = 128; epi = EPI_SIG;  bias = a0; }
    else if (z == 2) { A = g_hv; Wp = g_v2p; O = out_v; K = 128; epi = EPI_VMIX; bias = v0; }
    else             { A = g_hg; Wp = g_g2p; O = out_g; K = 256; epi = EPI_NONE; }

    const int n0 = blockIdx.x * 128;
    const int m0 = blockIdx.y * 128;
    float acc[4][4][4];
    zero_acc(acc);
    mainloop(A, Wp, K, m0, n0, smem_u32(smA), smem_u32(smB), acc);

    const int lane = threadIdx.x & 31;
    const int wid  = threadIdx.x >> 5;
    const int wm = (wid >> 2) * 64, wn = (wid & 3) * 32;
    const int tq = lane >> 2, tr = lane & 3;
    #pragma unroll
    for (int mf = 0; mf < 4; mf++) {
        #pragma unroll
        for (int nf = 0; nf < 4; nf++) {
            const int n = n0 + wn + nf * 8 + tr * 2;
            float bv0 = 0.0f, bv1 = 0.0f;
            if (bias) { bv0 = bias[n]; bv1 = bias[n + 1]; }
            #pragma unroll
            for (int h = 0; h < 2; h++) {
                const int m = m0 + wm + mf * 16 + tq + h * 8;
                float v0c = acc[mf][nf][h * 2], v1c = acc[mf][nf][h * 2 + 1];
                float o0, o1;
                if (epi == EPI_W) {
                    float y0 = bv0 + v0c, y1 = bv1 + v1c;
                    o0 = -(fmaxf(-y0, 0.0f) + log1pf(expf(-fabsf(y0)))) - 0.5f;
                    o1 = -(fmaxf(-y1, 0.0f) + log1pf(expf(-fabsf(y1)))) - 0.5f;
                } else if (epi == EPI_SIG) {
                    o0 = sigmoidf_(v0c + bv0); o1 = sigmoidf_(v1c + bv1);
                } else if (epi == EPI_VMIX) {
                    float s0 = sigmoidf_(bv0 + v0c), s1 = sigmoidf_(bv1 + v1c);
                    size_t ix = (size_t)m * Cdim + n;
                    float vg0 = g_vg[ix], vg1 = g_vg[ix + 1];
                    o0 = vg0 + (vfp[ix] - vg0) * s0;
                    o1 = vg1 + (vfp[ix + 1] - vg1) * s1;
                } else { o0 = v0c; o1 = v1c; }
                *(float2*)&O[(size_t)m * Cdim + n] = make_float2(o0, o1);
            }
        }
    }
}

// ---------------- elementwise producers (vectorized) ----------------
__global__ __launch_bounds__(256) void mix_kernel(
    const float* __restrict__ x, const float* __restrict__ vf,
    const float* __restrict__ mr, const float* __restrict__ mw,
    const float* __restrict__ mk, const float* __restrict__ mv,
    const float* __restrict__ ma, const float* __restrict__ mg,
    float* __restrict__ out_vf)
{
    size_t i4 = (size_t)blockIdx.x * blockDim.x + threadIdx.x;
    if (i4 >= BTC / 4) return;
    size_t idx = i4 * 4;
    int c   = (int)(idx & (Cdim - 1));
    int row = (int)(idx >> 11);
    int t   = row & (Tdim - 1);
    float4 xc = *(const float4*)&x[idx];
    float4 xp = (t == 0) ? make_float4(0.f, 0.f, 0.f, 0.f) : *(const float4*)&x[idx - Cdim];
    float4 xx = make_float4(xp.x - xc.x, xp.y - xc.y, xp.z - xc.z, xp.w - xc.w);
    *(float4*)&out_vf[idx] = *(const float4*)&vf[idx];
    #define DOMIX(dst, mm) do { \
        float4 mv_ = *(const float4*)&mm[c]; \
        __half2 h0_ = __floats2half2_rn(fmaf(xx.x, mv_.x, xc.x), fmaf(xx.y, mv_.y, xc.y)); \
        __half2 h1_ = __floats2half2_rn(fmaf(xx.z, mv_.z, xc.z), fmaf(xx.w, mv_.w, xc.w)); \
        uint2 u_; u_.x = *(uint32_t*)&h0_; u_.y = *(uint32_t*)&h1_; \
        *(uint2*)&dst[idx] = u_; \
    } while (0)
    DOMIX(g_xr, mr); DOMIX(g_xw, mw); DOMIX(g_xk, mk);
    DOMIX(g_xv, mv); DOMIX(g_xa, ma); DOMIX(g_xg, mg);
    #undef DOMIX
}

__global__ __launch_bounds__(256) void prep_big(
    const float* __restrict__ Wr, const float* __restrict__ Wk, const float* __restrict__ Wv)
{
    size_t i4 = (size_t)blockIdx.x * blockDim.x + threadIdx.x;
    if (i4 >= (size_t)Cdim * Cdim / 4) return;
    size_t idx = i4 * 4;
    int z = blockIdx.z;
    const float* W = (z == 0) ? Wr : (z == 1) ? Wk : Wv;
    __half* P = (z == 0) ? g_wr : (z == 1) ? g_wk : g_wv;
    float4 wv = *(const float4*)&W[idx];
    __half2 h0 = __floats2half2_rn(wv.x, wv.y);
    __half2 h1 = __floats2half2_rn(wv.z, wv.w);
    uint2 u; u.x = *(uint32_t*)&h0; u.y = *(uint32_t*)&h1;
    *(uint2*)&P[idx] = u;
}

// LoRA prep stage-1 weights, z-batched: [C,D] -> [Dp,C] half padded
__global__ __launch_bounds__(256) void prep_l1_all(
    const float* __restrict__ w1, const float* __restrict__ a1,
    const float* __restrict__ v1, const float* __restrict__ g1)
{
    const int z = blockIdx.z;
    const float* src = (z == 0) ? w1 : (z == 1) ? a1 : (z == 2) ? v1 : g1;
    __half* dst = (z == 0) ? g_w1p : (z == 1) ? g_a1p : (z == 2) ? g_v1p : g_g1p;
    const int D_ = (z == 0) ? 128 : (z == 1) ? 128 : (z == 2) ? 64 : 224;
    const int Dp = (z == 3) ? 256 : 128;
    size_t idx = (size_t)blockIdx.x * blockDim.x + threadIdx.x;
    if (idx >= (size_t)Dp * Cdim) return;
    int nn = (int)(idx / Cdim), k = (int)(idx % Cdim);
    dst[idx] = __float2half((nn < D_) ? src[(size_t)k * D_ + nn] : 0.0f);
}

// LoRA prep stage-2 weights, z-batched: [D,C] -> [C,Dp] half padded
__global__ __launch_bounds__(256) void prep_l2_all(
    const float* __restrict__ w2, const float* __restrict__ a2,
    const float* __restrict__ v2, const float* __restrict__ g2)
{
    const int z = blockIdx.z;
    const float* src = (z == 0) ? w2 : (z == 1) ? a2 : (z == 2) ? v2 : g2;
    __half* dst = (z == 0) ? g_w2p : (z == 1) ? g_a2p : (z == 2) ? g_v2p : g_g2p;
    const int D_ = (z == 0) ? 128 : (z == 1) ? 128 : (z == 2) ? 64 : 224;
    const int Dp = (z == 3) ? 256 : 128;
    size_t idx = (size_t)blockIdx.x * blockDim.x + threadIdx.x;
    if (idx >= (size_t)Cdim * Dp) return;
    int nn = (int)(idx / Dp), d = (int)(idx % Dp);
    dst[idx] = __float2half((d < D_) ? src[(size_t)d * Cdim + nn] : 0.0f);
}

// ---------------- kk / final k ----------------
__global__ __launch_bounds__(256) void kk_fin_kernel(
    const float* __restrict__ k_k, const float* __restrict__ k_a,
    const float* __restrict__ a_out,
    float* __restrict__ out_kk, float* __restrict__ out_k)
{
    int gw   = (blockIdx.x * blockDim.x + threadIdx.x) >> 5;
    int lane = threadIdx.x & 31;
    int row  = gw >> 5;
    int h    = gw & 31;
    if (row >= Mrows) return;
    int bse = row * Cdim + h * HSZ;
    int c0 = h * HSZ + lane, c1 = c0 + 32;
    float k0v = g_ko[bse + lane];
    float k1v = g_ko[bse + 32 + lane];
    float kk0 = k0v * k_k[c0];
    float kk1 = k1v * k_k[c1];
    float ss = kk0 * kk0 + kk1 * kk1;
    #pragma unroll
    for (int o = 16; o > 0; o >>= 1) ss += __shfl_xor_sync(0xFFFFFFFFu, ss, o);
    float inv = 1.0f / fmaxf(sqrtf(ss), 1e-12f);
    out_kk[bse + lane]      = kk0 * inv;
    out_kk[bse + 32 + lane] = kk1 * inv;
    float a0v = a_out[bse + lane];
    float a1v = a_out[bse + 32 + lane];
    out_k[bse + lane]      = k0v * fmaf(a0v - 1.0f, k_a[c0], 1.0f);
    out_k[bse + 32 + lane] = k1v * fmaf(a1v - 1.0f, k_a[c1], 1.0f);
}

// ---------------- launch ----------------
extern "C" void kernel_launch(void* const* d_in, const int* in_sizes, int n_in,
                              void* d_out, int out_size)
{
    const float* x   = (const float*)d_in[0];
    const float* vf  = (const float*)d_in[1];
    const float* x_r = (const float*)d_in[2];
    const float* x_w = (const float*)d_in[3];
    const float* x_k = (const float*)d_in[4];
    const float* x_v = (const float*)d_in[5];
    const float* x_a = (const float*)d_in[6];
    const float* x_g = (const float*)d_in[7];
    const float* w0  = (const float*)d_in[8];
    const float* w1  = (const float*)d_in[9];
    const float* w2  = (const float*)d_in[10];
    const float* a0  = (const float*)d_in[11];
    const float* a1  = (const float*)d_in[12];
    const float* a2  = (const float*)d_in[13];
    const float* v0  = (const float*)d_in[14];
    const float* v1  = (const float*)d_in[15];
    const float* v2  = (const float*)d_in[16];
    const float* g1  = (const float*)d_in[17];
    const float* g2  = (const float*)d_in[18];
    const float* k_k = (const float*)d_in[19];
    const float* k_a = (const float*)d_in[20];
    const float* Wr  = (const float*)d_in[21];
    const float* Wk  = (const float*)d_in[22];
    const float* Wv  = (const float*)d_in[23];
    (void)in_sizes; (void)n_in; (void)out_size;

    float* out = (float*)d_out;
    float* out_r  = out + 0 * BTC;
    float* out_w  = out + 1 * BTC;
    float* out_k  = out + 2 * BTC;
    float* out_v  = out + 3 * BTC;
    float* out_a  = out + 4 * BTC;
    float* out_g  = out + 5 * BTC;
    float* out_kk = out + 6 * BTC;
    float* out_vf = out + 7 * BTC;

    // 1. mix (fp16 activations, vectorized) + vf copy
    mix_kernel<<<(int)((BTC / 4 + 255) / 256), 256>>>(x, vf, x_r, x_w, x_k, x_v, x_a, x_g, out_vf);

    // 2. weight preps (z-batched)
    prep_big<<<dim3((unsigned)(((size_t)Cdim * Cdim / 4 + 255) / 256), 1, 3), 256>>>(Wr, Wk, Wv);
    prep_l1_all<<<dim3((unsigned)((256 * Cdim + 255) / 256), 1, 4), 256>>>(w1, a1, v1, g1);
    prep_l2_all<<<dim3((unsigned)(((size_t)Cdim * 256 + 255) / 256), 1, 4), 256>>>(w2, a2, v2, g2);

    // 3. all K=2048 GEMMs in one flat launch (big-3 first, s1 in the tail wave)
    gemm_k2048<<<3392, 256>>>(out_r);

    // 4. LoRA stage 2 (merged, fused epilogues)
    gemm_s2<<<dim3(Cdim / 128, Mrows / 128, 4), 256>>>(out_w, out_a, out_v, out_g, w0, a0, v0, vf);

    // 5. kk normalize + final k
    kk_fin_kernel<<<Mrows * 32 * 32 / 256, 256>>>(k_k, k_a, out_a, out_kk, out_k);
}

// round 13
// speedup vs baseline: 1.2295x; 1.0249x over previous
#include <cuda_runtime.h>
#include <cuda_fp16.h>
#include <math.h>
#include <stdint.h>

#define Bdim 2
#define Tdim 4096
#define Cdim 2048
#define HSZ  64
#define Mrows 8192
static const size_t BTC = (size_t)Mrows * Cdim;

// ---------------- scratch ----------------
__device__ __half g_xr[(size_t)Mrows * Cdim];
__device__ __half g_xw[(size_t)Mrows * Cdim];
__device__ __half g_xk[(size_t)Mrows * Cdim];
__device__ __half g_xv[(size_t)Mrows * Cdim];
__device__ __half g_xa[(size_t)Mrows * Cdim];
__device__ __half g_xg[(size_t)Mrows * Cdim];
__device__ __half g_wr[(size_t)Cdim * Cdim];
__device__ __half g_wk[(size_t)Cdim * Cdim];
__device__ __half g_wv[(size_t)Cdim * Cdim];
__device__ __half g_w1p[(size_t)128 * Cdim];
__device__ __half g_a1p[(size_t)128 * Cdim];
__device__ __half g_v1p[(size_t)128 * Cdim];
__device__ __half g_g1p[(size_t)256 * Cdim];
__device__ __half g_w2p[(size_t)Cdim * 128];
__device__ __half g_a2p[(size_t)Cdim * 128];
__device__ __half g_v2p[(size_t)Cdim * 128];
__device__ __half g_g2p[(size_t)Cdim * 256];
__device__ __half g_hw[(size_t)Mrows * 128];
__device__ __half g_ha[(size_t)Mrows * 128];
__device__ __half g_hv[(size_t)Mrows * 128];
__device__ __half g_hg[(size_t)Mrows * 256];
__device__ float  g_ko[(size_t)Mrows * Cdim];
__device__ float  g_vg[(size_t)Mrows * Cdim];

// ---------------- helpers ----------------
__device__ __forceinline__ float sigmoidf_(float y) { return 1.0f / (1.0f + expf(-y)); }

__device__ __forceinline__ uint32_t smem_u32(const void* p) {
    uint32_t a;
    asm("{ .reg .u64 t; cvta.to.shared.u64 t, %1; cvt.u32.u64 %0, t; }" : "=r"(a) : "l"(p));
    return a;
}
__device__ __forceinline__ void mma16(float* d, const uint32_t* a, const uint32_t* b) {
    asm volatile("mma.sync.aligned.m16n8k16.row.col.f32.f16.f16.f32 "
        "{%0,%1,%2,%3}, {%4,%5,%6,%7}, {%8,%9}, {%0,%1,%2,%3};"
        : "+f"(d[0]), "+f"(d[1]), "+f"(d[2]), "+f"(d[3])
        : "r"(a[0]), "r"(a[1]), "r"(a[2]), "r"(a[3]), "r"(b[0]), "r"(b[1]));
}
__device__ __forceinline__ void cpa16(uint32_t dst, const __half* src) {
    asm volatile("cp.async.cg.shared.global [%0], [%1], 16;"
        :: "r"(dst), "l"(__cvta_generic_to_global(src)));
}
#define CP_COMMIT() asm volatile("cp.async.commit_group;" ::: "memory")
#define CP_WAIT2()  asm volatile("cp.async.wait_group 2;" ::: "memory")
#define LDSM4(r0,r1,r2,r3,addr) \
    asm volatile("ldmatrix.sync.aligned.m8n8.x4.shared.b16 {%0,%1,%2,%3}, [%4];" \
        : "=r"(r0), "=r"(r1), "=r"(r2), "=r"(r3) : "r"(addr))

// stage size: 128 rows x 32 halves = 8192 bytes per operand; 4 stages
#define STGB 8192
#define NSTG 4

// ---------------- mainloop: 128x128 tile, KC=32, 4-stage cp.async, ldmatrix ----
__device__ __forceinline__ void mainloop(
    const __half* __restrict__ A, const __half* __restrict__ Bm,
    int K, int m0, int n0, uint32_t sA, uint32_t sB, float acc[4][4][4])
{
    const int tid  = threadIdx.x;
    const int lane = tid & 31;
    const int wid  = tid >> 5;
    const int wm   = (wid >> 2) * 64;
    const int wn   = (wid & 3) * 32;

    const int rA  = tid >> 2;
    const int cA  = tid & 3;
    const int rA2 = rA + 64;
    const uint32_t o0 = rA  * 64 + ((cA ^ ((rA  >> 1) & 3)) * 16);
    const uint32_t o1 = rA2 * 64 + ((cA ^ ((rA2 >> 1) & 3)) * 16);
    const __half* Ag0 = A  + (size_t)(m0 + rA)  * K + cA * 8;
    const __half* Ag1 = A  + (size_t)(m0 + rA2) * K + cA * 8;
    const __half* Bg0 = Bm + (size_t)(n0 + rA)  * K + cA * 8;
    const __half* Bg1 = Bm + (size_t)(n0 + rA2) * K + cA * 8;

    const int rowadd = (lane & 7) + ((lane >> 3) & 1) * 8;
    const int swz    = (rowadd >> 1) & 3;
    const int cbit   = lane >> 4;

    const int NIT = K >> 5;
    #pragma unroll
    for (int s = 0; s < 3; s++) {
        const int k0 = s << 5;
        cpa16(sA + s * STGB + o0, Ag0 + k0);
        cpa16(sA + s * STGB + o1, Ag1 + k0);
        cpa16(sB + s * STGB + o0, Bg0 + k0);
        cpa16(sB + s * STGB + o1, Bg1 + k0);
        CP_COMMIT();
    }
    CP_WAIT2();
    __syncthreads();

    int s = 0;
    for (int it = 0; it < NIT; it++) {
        const uint32_t bA = sA + s * STGB;
        const uint32_t bB = sB + s * STGB;
        #pragma unroll
        for (int kb = 0; kb < 2; kb++) {
            const uint32_t choff = (uint32_t)((((kb << 1) + cbit) ^ swz) * 16);
            const uint32_t aaddr = bA + (wm + rowadd) * 64 + choff;
            const uint32_t baddr = bB + (wn + rowadd) * 64 + choff;
            uint32_t af[4][4], br[2][4];
            #pragma unroll
            for (int mf = 0; mf < 4; mf++)
                LDSM4(af[mf][0], af[mf][1], af[mf][2], af[mf][3], aaddr + mf * 1024);
            #pragma unroll
            for (int nb = 0; nb < 2; nb++)
                LDSM4(br[nb][0], br[nb][1], br[nb][2], br[nb][3], baddr + nb * 1024);
            #pragma unroll
            for (int mf = 0; mf < 4; mf++) {
                #pragma unroll
                for (int nf = 0; nf < 4; nf++) {
                    uint32_t b2[2] = { br[nf >> 1][nf & 1], br[nf >> 1][(nf & 1) + 2] };
                    mma16(acc[mf][nf], af[mf], b2);
                }
            }
        }
        if (it + 3 < NIT) {
            int s2 = s + 3; if (s2 >= NSTG) s2 -= NSTG;
            const int k0 = (it + 3) << 5;
            cpa16(sA + s2 * STGB + o0, Ag0 + k0);
            cpa16(sA + s2 * STGB + o1, Ag1 + k0);
            cpa16(sB + s2 * STGB + o0, Bg0 + k0);
            cpa16(sB + s2 * STGB + o1, Bg1 + k0);
        }
        CP_COMMIT();
        CP_WAIT2();
        __syncthreads();
        if (++s == NSTG) s = 0;
    }
}

#define EPI_NONE 0
#define EPI_TANH 1
#define EPI_W    2
#define EPI_SIG  3
#define EPI_VMIX 4

__device__ __forceinline__ void zero_acc(float acc[4][4][4]) {
    #pragma unroll
    for (int i = 0; i < 4; i++)
        #pragma unroll
        for (int j = 0; j < 4; j++)
            #pragma unroll
            for (int q = 0; q < 4; q++) acc[i][j][q] = 0.0f;
}

// ---------------- merged K=2048 GEMMs: big-3 (3072 CTAs) + LoRA s1 (320) ------
__global__ __launch_bounds__(256, 2) void gemm_k2048(float* __restrict__ out_r)
{
    __shared__ __half smA[NSTG * STGB / 2];
    __shared__ __half smB[NSTG * STGB / 2];
    const int bid = blockIdx.x;

    const __half* A;
    const __half* Wp;
    float* Of = nullptr;
    __half* Oh = nullptr;
    int m0, n0 = 0, Nst = 2048, epi = EPI_NONE;

    if (bid < 3072) {
        const int g = bid >> 10, rem = bid & 1023;
        m0 = (rem >> 4) * 128;
        n0 = (rem & 15) * 128;
        A  = (g == 0) ? g_xr : (g == 1) ? g_xk : g_xv;
        Wp = (g == 0) ? g_wr : (g == 1) ? g_wk : g_wv;
        Of = (g == 0) ? out_r : (g == 1) ? g_ko : g_vg;
    } else {
        const int sid = bid - 3072;
        const int job = sid >> 6;                 // 0..4
        m0 = (sid & 63) * 128;
        if (job == 0)      { A = g_xw; Wp = g_w1p; Oh = g_hw; Nst = 128; epi = EPI_TANH; }
        else if (job == 1) { A = g_xa; Wp = g_a1p; Oh = g_ha; Nst = 128; }
        else if (job == 2) { A = g_xv; Wp = g_v1p; Oh = g_hv; Nst = 128; }
        else               { A = g_xg; Wp = g_g1p; Oh = g_hg; Nst = 256; epi = EPI_SIG;
                             n0 = (job == 4) ? 128 : 0; }
    }

    float acc[4][4][4];
    zero_acc(acc);
    mainloop(A, Wp, Cdim, m0, n0, smem_u32(smA), smem_u32(smB), acc);

    const int lane = threadIdx.x & 31;
    const int wid  = threadIdx.x >> 5;
    const int wm = (wid >> 2) * 64, wn = (wid & 3) * 32;
    const int tq = lane >> 2, tr = lane & 3;

    if (Of) {
        #pragma unroll
        for (int mf = 0; mf < 4; mf++) {
            #pragma unroll
            for (int nf = 0; nf < 4; nf++) {
                const int n = n0 + wn + nf * 8 + tr * 2;
                #pragma unroll
                for (int h = 0; h < 2; h++) {
                    const int m = m0 + wm + mf * 16 + tq + h * 8;
                    *(float2*)&Of[(size_t)m * 2048 + n] =
                        make_float2(acc[mf][nf][h * 2], acc[mf][nf][h * 2 + 1]);
                }
            }
        }
    } else {
        #pragma unroll
        for (int mf = 0; mf < 4; mf++) {
            #pragma unroll
            for (int nf = 0; nf < 4; nf++) {
                const int n = n0 + wn + nf * 8 + tr * 2;
                #pragma unroll
                for (int h = 0; h < 2; h++) {
                    const int m = m0 + wm + mf * 16 + tq + h * 8;
                    float o0 = acc[mf][nf][h * 2], o1 = acc[mf][nf][h * 2 + 1];
                    if (epi == EPI_TANH)     { o0 = tanhf(o0); o1 = tanhf(o1); }
                    else if (epi == EPI_SIG) { o0 = sigmoidf_(o0); o1 = sigmoidf_(o1); }
                    *(__half2*)&Oh[(size_t)m * Nst + n] = __floats2half2_rn(o0, o1);
                }
            }
        }
    }
}

// ---------------- LoRA stage-2 (z-merged; z==1 fuses a + k_final + kk) --------
__global__ __launch_bounds__(256, 2) void gemm_s2(
    float* __restrict__ out_w, float* __restrict__ out_a,
    float* __restrict__ out_v, float* __restrict__ out_g,
    float* __restrict__ out_k, float* __restrict__ out_kk,
    const float* __restrict__ w0, const float* __restrict__ a0,
    const float* __restrict__ v0, const float* __restrict__ vfp,
    const float* __restrict__ k_k, const float* __restrict__ k_a)
{
    __shared__ __half smA[NSTG * STGB / 2];
    __shared__ __half smB[NSTG * STGB / 2];
    __shared__ float smRed[8][64];
    const int z = blockIdx.z;
    const __half* A;
    const __half* Wp;
    float* O;
    const float* bias = nullptr;
    int K, epi;
    if (z == 0)      { A = g_hw; Wp = g_w2p; O = out_w; K = 128; epi = EPI_W;    bias = w0; }
    else if (z == 1) { A = g_ha; Wp = g_a2p; O = out_a; K = 128; epi = EPI_SIG;  bias = a0; }
    else if (z == 2) { A = g_hv; Wp = g_v2p; O = out_v; K = 128; epi = EPI_VMIX; bias = v0; }
    else             { A = g_hg; Wp = g_g2p; O = out_g; K = 256; epi = EPI_NONE; }

    const int n0 = blockIdx.x * 128;
    const int m0 = blockIdx.y * 128;
    float acc[4][4][4];
    zero_acc(acc);
    mainloop(A, Wp, K, m0, n0, smem_u32(smA), smem_u32(smB), acc);

    const int lane = threadIdx.x & 31;
    const int wid  = threadIdx.x >> 5;
    const int wm = (wid >> 2) * 64, wn = (wid & 3) * 32;
    const int tq = lane >> 2, tr = lane & 3;

    if (z == 1) {
        // fused: a = sigmoid(a0+acc); k_final = ko*(1+(a-1)*k_a); kk = normalize(ko*k_k)
        float ss[4][2] = {};
        #pragma unroll
        for (int mf = 0; mf < 4; mf++) {
            #pragma unroll
            for (int nf = 0; nf < 4; nf++) {
                const int n = n0 + wn + nf * 8 + tr * 2;
                const float bv0 = bias[n], bv1 = bias[n + 1];
                const float kc0 = k_k[n], kc1 = k_k[n + 1];
                const float ka0 = k_a[n], ka1 = k_a[n + 1];
                #pragma unroll
                for (int h = 0; h < 2; h++) {
                    const int m = m0 + wm + mf * 16 + tq + h * 8;
                    const size_t ix = (size_t)m * Cdim + n;
                    float a0v = sigmoidf_(acc[mf][nf][h * 2]     + bv0);
                    float a1v = sigmoidf_(acc[mf][nf][h * 2 + 1] + bv1);
                    *(float2*)&out_a[ix] = make_float2(a0v, a1v);
                    float2 kr = *(const float2*)&g_ko[ix];
                    *(float2*)&out_k[ix] = make_float2(
                        kr.x * fmaf(a0v - 1.0f, ka0, 1.0f),
                        kr.y * fmaf(a1v - 1.0f, ka1, 1.0f));
                    float kk0 = kr.x * kc0, kk1 = kr.y * kc1;
                    ss[mf][h] += kk0 * kk0 + kk1 * kk1;
                }
            }
        }
        #pragma unroll
        for (int mf = 0; mf < 4; mf++)
            #pragma unroll
            for (int h = 0; h < 2; h++) {
                ss[mf][h] += __shfl_xor_sync(0xFFFFFFFFu, ss[mf][h], 1);
                ss[mf][h] += __shfl_xor_sync(0xFFFFFFFFu, ss[mf][h], 2);
            }
        if (tr == 0) {
            #pragma unroll
            for (int mf = 0; mf < 4; mf++)
                #pragma unroll
                for (int h = 0; h < 2; h++)
                    smRed[wid][mf * 16 + h * 8 + tq] = ss[mf][h];
        }
        __syncthreads();
        float inv[4][2];
        #pragma unroll
        for (int mf = 0; mf < 4; mf++)
            #pragma unroll
            for (int h = 0; h < 2; h++) {
                const int ml = mf * 16 + h * 8 + tq;
                float t = smRed[wid][ml] + smRed[wid ^ 1][ml];
                inv[mf][h] = 1.0f / fmaxf(sqrtf(t), 1e-12f);
            }
        #pragma unroll
        for (int mf = 0; mf < 4; mf++) {
            #pragma unroll
            for (int nf = 0; nf < 4; nf++) {
                const int n = n0 + wn + nf * 8 + tr * 2;
                const float kc0 = k_k[n], kc1 = k_k[n + 1];
                #pragma unroll
                for (int h = 0; h < 2; h++) {
                    const int m = m0 + wm + mf * 16 + tq + h * 8;
                    const size_t ix = (size_t)m * Cdim + n;
                    float2 kr = *(const float2*)&g_ko[ix];
                    *(float2*)&out_kk[ix] = make_float2(
                        kr.x * kc0 * inv[mf][h], kr.y * kc1 * inv[mf][h]);
                }
            }
        }
        return;
    }

    #pragma unroll
    for (int mf = 0; mf < 4; mf++) {
        #pragma unroll
        for (int nf = 0; nf < 4; nf++) {
            const int n = n0 + wn + nf * 8 + tr * 2;
            float bv0 = 0.0f, bv1 = 0.0f;
            if (bias) { bv0 = bias[n]; bv1 = bias[n + 1]; }
            #pragma unroll
            for (int h = 0; h < 2; h++) {
                const int m = m0 + wm + mf * 16 + tq + h * 8;
                float v0c = acc[mf][nf][h * 2], v1c = acc[mf][nf][h * 2 + 1];
                float o0, o1;
                if (epi == EPI_W) {
                    float y0 = bv0 + v0c, y1 = bv1 + v1c;
                    o0 = -(fmaxf(-y0, 0.0f) + log1pf(expf(-fabsf(y0)))) - 0.5f;
                    o1 = -(fmaxf(-y1, 0.0f) + log1pf(expf(-fabsf(y1)))) - 0.5f;
                } else if (epi == EPI_VMIX) {
                    float s0 = sigmoidf_(bv0 + v0c), s1 = sigmoidf_(bv1 + v1c);
                    size_t ix = (size_t)m * Cdim + n;
                    float vg0 = g_vg[ix], vg1 = g_vg[ix + 1];
                    o0 = vg0 + (vfp[ix] - vg0) * s0;
                    o1 = vg1 + (vfp[ix + 1] - vg1) * s1;
                } else { o0 = v0c; o1 = v1c; }
                *(float2*)&O[(size_t)m * Cdim + n] = make_float2(o0, o1);
            }
        }
    }
}

// ---------------- elementwise producers (vectorized) ----------------
__global__ __launch_bounds__(256) void mix_kernel(
    const float* __restrict__ x, const float* __restrict__ vf,
    const float* __restrict__ mr, const float* __restrict__ mw,
    const float* __restrict__ mk, const float* __restrict__ mv,
    const float* __restrict__ ma, const float* __restrict__ mg,
    float* __restrict__ out_vf)
{
    size_t i4 = (size_t)blockIdx.x * blockDim.x + threadIdx.x;
    if (i4 >= BTC / 4) return;
    size_t idx = i4 * 4;
    int c   = (int)(idx & (Cdim - 1));
    int row = (int)(idx >> 11);
    int t   = row & (Tdim - 1);
    float4 xc = *(const float4*)&x[idx];
    float4 xp = (t == 0) ? make_float4(0.f, 0.f, 0.f, 0.f) : *(const float4*)&x[idx - Cdim];
    float4 xx = make_float4(xp.x - xc.x, xp.y - xc.y, xp.z - xc.z, xp.w - xc.w);
    *(float4*)&out_vf[idx] = *(const float4*)&vf[idx];
    #define DOMIX(dst, mm) do { \
        float4 mv_ = *(const float4*)&mm[c]; \
        __half2 h0_ = __floats2half2_rn(fmaf(xx.x, mv_.x, xc.x), fmaf(xx.y, mv_.y, xc.y)); \
        __half2 h1_ = __floats2half2_rn(fmaf(xx.z, mv_.z, xc.z), fmaf(xx.w, mv_.w, xc.w)); \
        uint2 u_; u_.x = *(uint32_t*)&h0_; u_.y = *(uint32_t*)&h1_; \
        *(uint2*)&dst[idx] = u_; \
    } while (0)
    DOMIX(g_xr, mr); DOMIX(g_xw, mw); DOMIX(g_xk, mk);
    DOMIX(g_xv, mv); DOMIX(g_xa, ma); DOMIX(g_xg, mg);
    #undef DOMIX
}

__global__ __launch_bounds__(256) void prep_big(
    const float* __restrict__ Wr, const float* __restrict__ Wk, const float* __restrict__ Wv)
{
    size_t i4 = (size_t)blockIdx.x * blockDim.x + threadIdx.x;
    if (i4 >= (size_t)Cdim * Cdim / 4) return;
    size_t idx = i4 * 4;
    int z = blockIdx.z;
    const float* W = (z == 0) ? Wr : (z == 1) ? Wk : Wv;
    __half* P = (z == 0) ? g_wr : (z == 1) ? g_wk : g_wv;
    float4 wv = *(const float4*)&W[idx];
    __half2 h0 = __floats2half2_rn(wv.x, wv.y);
    __half2 h1 = __floats2half2_rn(wv.z, wv.w);
    uint2 u; u.x = *(uint32_t*)&h0; u.y = *(uint32_t*)&h1;
    *(uint2*)&P[idx] = u;
}

// tiled transpose prep: src [C, D_] -> dst [Dp, C] half, zero-padded (stage-1 weights)
__global__ void prep_l1t(
    const float* __restrict__ w1, const float* __restrict__ a1,
    const float* __restrict__ v1, const float* __restrict__ g1)
{
    __shared__ float sm[32][33];
    const int z = blockIdx.z;
    const float* src = (z == 0) ? w1 : (z == 1) ? a1 : (z == 2) ? v1 : g1;
    __half* dst = (z == 0) ? g_w1p : (z == 1) ? g_a1p : (z == 2) ? g_v1p : g_g1p;
    const int D_ = (z == 0) ? 128 : (z == 1) ? 128 : (z == 2) ? 64 : 224;
    const int Dp = (z == 3) ? 256 : 128;
    const int nn_t = blockIdx.y * 32;
    if (nn_t >= Dp) return;
    const int k_t = blockIdx.x * 32;
    const int tx = threadIdx.x & 31, ty = threadIdx.x >> 5;   // 32x8
    #pragma unroll
    for (int i = 0; i < 4; i++) {
        const int k = k_t + ty + i * 8;
        const int nn = nn_t + tx;
        sm[ty + i * 8][tx] = (nn < D_) ? src[(size_t)k * D_ + nn] : 0.0f;
    }
    __syncthreads();
    #pragma unroll
    for (int i = 0; i < 4; i++) {
        const int nn = nn_t + ty + i * 8;
        const int k = k_t + tx;
        dst[(size_t)nn * Cdim + k] = __float2half(sm[tx][ty + i * 8]);
    }
}

// tiled transpose prep: src [D_, C] -> dst [C, Dp] half, zero-padded (stage-2 weights)
__global__ void prep_l2t(
    const float* __restrict__ w2, const float* __restrict__ a2,
    const float* __restrict__ v2, const float* __restrict__ g2)
{
    __shared__ float sm[32][33];
    const int z = blockIdx.z;
    const float* src = (z == 0) ? w2 : (z == 1) ? a2 : (z == 2) ? v2 : g2;
    __half* dst = (z == 0) ? g_w2p : (z == 1) ? g_a2p : (z == 2) ? g_v2p : g_g2p;
    const int D_ = (z == 0) ? 128 : (z == 1) ? 128 : (z == 2) ? 64 : 224;
    const int Dp = (z == 3) ? 256 : 128;
    const int d_t = blockIdx.y * 32;
    if (d_t >= Dp) return;
    const int nn_t = blockIdx.x * 32;
    const int tx = threadIdx.x & 31, ty = threadIdx.x >> 5;
    #pragma unroll
    for (int i = 0; i < 4; i++) {
        const int d = d_t + ty + i * 8;
        const int nn = nn_t + tx;
        sm[ty + i * 8][tx] = (d < D_) ? src[(size_t)d * Cdim + nn] : 0.0f;
    }
    __syncthreads();
    #pragma unroll
    for (int i = 0; i < 4; i++) {
        const int nn = nn_t + ty + i * 8;
        const int d = d_t + tx;
        dst[(size_t)nn * Dp + d] = __float2half(sm[tx][ty + i * 8]);
    }
}

// ---------------- launch ----------------
extern "C" void kernel_launch(void* const* d_in, const int* in_sizes, int n_in,
                              void* d_out, int out_size)
{
    const float* x   = (const float*)d_in[0];
    const float* vf  = (const float*)d_in[1];
    const float* x_r = (const float*)d_in[2];
    const float* x_w = (const float*)d_in[3];
    const float* x_k = (const float*)d_in[4];
    const float* x_v = (const float*)d_in[5];
    const float* x_a = (const float*)d_in[6];
    const float* x_g = (const float*)d_in[7];
    const float* w0  = (const float*)d_in[8];
    const float* w1  = (const float*)d_in[9];
    const float* w2  = (const float*)d_in[10];
    const float* a0  = (const float*)d_in[11];
    const float* a1  = (const float*)d_in[12];
    const float* a2  = (const float*)d_in[13];
    const float* v0  = (const float*)d_in[14];
    const float* v1  = (const float*)d_in[15];
    const float* v2  = (const float*)d_in[16];
    const float* g1  = (const float*)d_in[17];
    const float* g2  = (const float*)d_in[18];
    const float* k_k = (const float*)d_in[19];
    const float* k_a = (const float*)d_in[20];
    const float* Wr  = (const float*)d_in[21];
    const float* Wk  = (const float*)d_in[22];
    const float* Wv  = (const float*)d_in[23];
    (void)in_sizes; (void)n_in; (void)out_size;

    float* out = (float*)d_out;
    float* out_r  = out + 0 * BTC;
    float* out_w  = out + 1 * BTC;
    float* out_k  = out + 2 * BTC;
    float* out_v  = out + 3 * BTC;
    float* out_a  = out + 4 * BTC;
    float* out_g  = out + 5 * BTC;
    float* out_kk = out + 6 * BTC;
    float* out_vf = out + 7 * BTC;

    // 1. mix (fp16 activations, vectorized) + vf copy
    mix_kernel<<<(int)((BTC / 4 + 255) / 256), 256>>>(x, vf, x_r, x_w, x_k, x_v, x_a, x_g, out_vf);

    // 2. weight preps (z-batched; tiled transposes)
    prep_big<<<dim3((unsigned)(((size_t)Cdim * Cdim / 4 + 255) / 256), 1, 3), 256>>>(Wr, Wk, Wv);
    prep_l1t<<<dim3(Cdim / 32, 8, 4), 256>>>(w1, a1, v1, g1);
    prep_l2t<<<dim3(Cdim / 32, 8, 4), 256>>>(w2, a2, v2, g2);

    // 3. all K=2048 GEMMs in one flat launch (big-3 first, s1 in the tail wave)
    gemm_k2048<<<3392, 256>>>(out_r);

    // 4. LoRA stage 2 (merged, fused epilogues; z==1 also emits k_final + kk)
    gemm_s2<<<dim3(Cdim / 128, Mrows / 128, 4), 256>>>(
        out_w, out_a, out_v, out_g, out_k, out_kk, w0, a0, v0, vf, k_k, k_a);
}